// round 15
// baseline (speedup 1.0000x reference)
#include <cuda_runtime.h>
#include <cuda_fp16.h>
#include <math.h>
#include <float.h>
#include <stdint.h>

#define BATCH   2
#define SEQ     2048
#define HID     2048
#define NHEADS  16
#define HD      128

// ---------------- static scratch (no allocations allowed) ----------------
__device__ __half g_Qh   [BATCH * NHEADS * SEQ * HD];   // [B,NH,S,D]
__device__ __half g_Kh   [BATCH * NHEADS * SEQ * HD];
__device__ __half g_Vh   [BATCH * NHEADS * SEQ * HD];   // [B,NH,S,D] (natural)
__device__ __half g_ctxh [BATCH * SEQ * HID];           // [B,S,H]
__device__ __half g_xh   [BATCH * SEQ * HID];           // fp16 x
__device__ __half g_wqkvh[3 * HID * HID];               // [3H,H]  qkv_w^T fp16
__device__ __half g_dwh  [HID * HID];                   // [H,H]   dense_w^T fp16
__device__ float  g_bias [NHEADS * SEQ];                // bias[h][q-k] * log2(e)
__device__ float  g_cos  [SEQ * 64];
__device__ float  g_sin  [SEQ * 64];

// ======================= helpers =======================
__device__ __forceinline__ uint32_t smem_u32(const void* p) {
    uint32_t a;
    asm("{ .reg .u64 t; cvta.to.shared.u64 t, %1; cvt.u32.u64 %0, t; }"
        : "=r"(a) : "l"(p));
    return a;
}
__device__ __forceinline__ void cp16(uint32_t s, const void* g) {
    asm volatile("cp.async.cg.shared.global [%0], [%1], 16;" :: "r"(s), "l"(g));
}
__device__ __forceinline__ void cp4(uint32_t s, const void* g) {
    asm volatile("cp.async.ca.shared.global [%0], [%1], 4;" :: "r"(s), "l"(g));
}
#define CP_COMMIT() asm volatile("cp.async.commit_group;" ::: "memory")
#define CP_WAIT2()  asm volatile("cp.async.wait_group 2;"  ::: "memory")
#define CP_WAIT1()  asm volatile("cp.async.wait_group 1;"  ::: "memory")
#define CP_WAIT0()  asm volatile("cp.async.wait_group 0;"  ::: "memory")

__device__ __forceinline__ uint32_t packh2(float x, float y) {
    __half2 h = __floats2half2_rn(x, y);
    return *(uint32_t*)&h;
}

// ldmatrix x4: loads 4 8x8 f16 matrices; lane groups 0-7/8-15/16-23/24-31 give row addrs.
__device__ __forceinline__ void ldm_x4(uint32_t* r, uint32_t addr) {
    asm volatile("ldmatrix.sync.aligned.m8n8.x4.shared.b16 {%0,%1,%2,%3}, [%4];"
        : "=r"(r[0]), "=r"(r[1]), "=r"(r[2]), "=r"(r[3]) : "r"(addr));
}
// trans variant: each 8x8 tile transposed in-flight.
__device__ __forceinline__ void ldm_x4_t(uint32_t* r, uint32_t addr) {
    asm volatile("ldmatrix.sync.aligned.m8n8.x4.trans.shared.b16 {%0,%1,%2,%3}, [%4];"
        : "=r"(r[0]), "=r"(r[1]), "=r"(r[2]), "=r"(r[3]) : "r"(addr));
}

// fp16 mma: D(f32) += A(f16 m16k16, row) * B(f16 k16n8, col)
__device__ __forceinline__ void mma16816(float* d, const uint32_t* a, const uint32_t* b) {
    asm volatile(
        "mma.sync.aligned.m16n8k16.row.col.f32.f16.f16.f32 "
        "{%0,%1,%2,%3}, {%4,%5,%6,%7}, {%8,%9}, {%0,%1,%2,%3};"
        : "+f"(d[0]), "+f"(d[1]), "+f"(d[2]), "+f"(d[3])
        : "r"(a[0]), "r"(a[1]), "r"(a[2]), "r"(a[3]), "r"(b[0]), "r"(b[1]));
}

// ======================= f32 -> f16 convert (elementwise) =======================
__global__ __launch_bounds__(256) void convert_h_kernel(
    const float* __restrict__ in, __half* __restrict__ out)
{
    int i = blockIdx.x * blockDim.x + threadIdx.x;
    float4 v = ((const float4*)in)[i];
    __half2* o = (__half2*)out;
    o[2 * i]     = __floats2half2_rn(v.x, v.y);
    o[2 * i + 1] = __floats2half2_rn(v.z, v.w);
}

// ======================= f32 [R][C] -> f16 [C][R] transpose =======================
__global__ __launch_bounds__(256) void transpose_h_kernel(
    const float* __restrict__ in, __half* __restrict__ out, int R, int C)
{
    __shared__ float t[32][33];
    int bx = blockIdx.x * 32, by = blockIdx.y * 32;
    int tx = threadIdx.x & 31, ty = threadIdx.x >> 5;
#pragma unroll
    for (int i = 0; i < 32; i += 8)
        t[ty + i][tx] = in[(size_t)(by + ty + i) * C + bx + tx];
    __syncthreads();
#pragma unroll
    for (int i = 0; i < 32; i += 8)
        out[(size_t)(bx + ty + i) * R + by + tx] = __float2half_rn(t[tx][ty + i]);
}

// ======================= RoPE cos/sin table =======================
__global__ __launch_bounds__(256) void rope_table_kernel()
{
    int idx = blockIdx.x * blockDim.x + threadIdx.x;   // SEQ*64
    int s = idx >> 6, d = idx & 63;
    float inv = powf(10000.f, -(float)d * (1.f / 64.f));
    float sn, cs;
    sincosf((float)s * inv, &sn, &cs);
    g_cos[idx] = cs;
    g_sin[idx] = sn;
}

// ======================= fp16 mma GEMM: 128x128, BK=32h, 4 stages, occ2 ============
// ROPE=true: epilogue stages C in smem (fp16), applies RoPE + head-split, writes
// directly to g_Qh/g_Kh/g_Vh in [B,NH,S,D]. ROPE=false: plain C output (OutT).
#define GBM 128
#define GBN 128
#define GBKH 32                      // k halves per chunk
#define GPITCH 40                    // halves; 80B rows -> conflict-free ldmatrix
#define STG_HALFS (2 * 128 * GPITCH) // A + B = 10240 halves = 20480 B
#define GEMM_SMEM (4 * STG_HALFS * 2)   // 81920 B -> 2 CTAs/SM
#define EPI_PITCH 136                // fp16 epilogue staging pitch

template <typename OutT, bool ROPE>
__global__ __launch_bounds__(256, 2) void gemm_h(
    const __half* __restrict__ A, const __half* __restrict__ Bt,
    OutT* __restrict__ C, int M, int N, int K)
{
    extern __shared__ __half smh[];
    const int tid  = threadIdx.x;
    const int warp = tid >> 5, lane = tid & 31;
    const int wm = (warp >> 2) * 64;
    const int wn = (warp & 3) * 32;
    const int r  = lane >> 2;
    const int q  = lane & 3;
    const int row0 = blockIdx.y * GBM;
    const int col0 = blockIdx.x * GBN;
    const uint32_t sb = smem_u32(smh);
    const int NC = K / GBKH;

    const int aOff = (wm + (lane & 15)) * GPITCH + ((lane >> 4) & 1) * 8;
    const int bOff = (wn + (lane & 7) + ((lane >> 4) & 1) * 8) * GPITCH
                   + ((lane >> 3) & 1) * 8;

    float cf[4][4][4];
#pragma unroll
    for (int i = 0; i < 4; i++)
#pragma unroll
        for (int j = 0; j < 4; j++)
#pragma unroll
            for (int t = 0; t < 4; t++) cf[i][j][t] = 0.f;

    const int lrow = tid >> 1;
    const int lseg = (tid & 1) * 2;

    auto load_stage = [&](int c, int s) {
        uint32_t base = sb + (uint32_t)(s * STG_HALFS) * 2u;
#pragma unroll
        for (int j = 0; j < 2; j++) {
            int seg = lseg + j;
            cp16(base + (uint32_t)(lrow * GPITCH + seg * 8) * 2u,
                 A + (size_t)(row0 + lrow) * K + c * GBKH + seg * 8);
            cp16(base + (uint32_t)(128 * GPITCH + lrow * GPITCH + seg * 8) * 2u,
                 Bt + (size_t)(col0 + lrow) * K + c * GBKH + seg * 8);
        }
        CP_COMMIT();
    };

    load_stage(0, 0);
    load_stage(1, 1);
    load_stage(2, 2);

    for (int c = 0; c < NC; ++c) {
        CP_WAIT2();
        __syncthreads();
        int nc = c + 3;
        if (nc < NC) load_stage(nc, nc & 3); else CP_COMMIT();

        uint32_t aBase = sb + (uint32_t)((c & 3) * STG_HALFS) * 2u;
        uint32_t bBase = aBase + (uint32_t)(128 * GPITCH) * 2u;
#pragma unroll
        for (int step = 0; step < 2; step++) {
            const int kk = step * 16;
            uint32_t af[4][4], bt[2][4];
#pragma unroll
            for (int mt = 0; mt < 4; mt++)
                ldm_x4(af[mt], aBase + (uint32_t)(aOff + mt * 16 * GPITCH + kk) * 2u);
#pragma unroll
            for (int p = 0; p < 2; p++)
                ldm_x4(bt[p], bBase + (uint32_t)(bOff + p * 16 * GPITCH + kk) * 2u);
#pragma unroll
            for (int mt = 0; mt < 4; mt++) {
                mma16816(cf[mt][0], af[mt], &bt[0][0]);
                mma16816(cf[mt][1], af[mt], &bt[0][2]);
                mma16816(cf[mt][2], af[mt], &bt[1][0]);
                mma16816(cf[mt][3], af[mt], &bt[1][2]);
            }
        }
    }

    if (!ROPE) {
        // plain epilogue
#pragma unroll
        for (int mt = 0; mt < 4; mt++) {
            int row = row0 + wm + mt * 16 + r;
#pragma unroll
            for (int nt = 0; nt < 4; nt++) {
                int col = col0 + wn + nt * 8 + 2 * q;
                if (sizeof(OutT) == 2) {
                    *(__half2*)((__half*)C + (size_t)row * N + col) =
                        __floats2half2_rn(cf[mt][nt][0], cf[mt][nt][1]);
                    *(__half2*)((__half*)C + (size_t)(row + 8) * N + col) =
                        __floats2half2_rn(cf[mt][nt][2], cf[mt][nt][3]);
                } else {
                    *(float2*)((float*)C + (size_t)row * N + col) =
                        make_float2(cf[mt][nt][0], cf[mt][nt][1]);
                    *(float2*)((float*)C + (size_t)(row + 8) * N + col) =
                        make_float2(cf[mt][nt][2], cf[mt][nt][3]);
                }
            }
        }
    } else {
        // RoPE + head-split epilogue: tile spans exactly one head.
        __syncthreads();                 // all warps done with stage buffers
        __half* ct = smh;                // [128][EPI_PITCH] fp16 staging
#pragma unroll
        for (int mt = 0; mt < 4; mt++) {
            int rl = wm + mt * 16 + r;
#pragma unroll
            for (int nt = 0; nt < 4; nt++) {
                int cl = wn + nt * 8 + 2 * q;
                *(__half2*)&ct[(size_t)rl * EPI_PITCH + cl] =
                    __floats2half2_rn(cf[mt][nt][0], cf[mt][nt][1]);
                *(__half2*)&ct[(size_t)(rl + 8) * EPI_PITCH + cl] =
                    __floats2half2_rn(cf[mt][nt][2], cf[mt][nt][3]);
            }
        }
        __syncthreads();

        const int region = col0 >> 11;           // 0=Q, 1=K, 2=V
        const int head   = (col0 & 2047) >> 7;
        __half* dst = (region == 0) ? g_Qh : (region == 1) ? g_Kh : g_Vh;

        for (int idx = tid; idx < 128 * 64; idx += 256) {
            int rl = idx >> 6, d = idx & 63;
            int grow = row0 + rl;                // b*SEQ + s
            int bq = grow >> 11, sq = grow & (SEQ - 1);
            float t1 = __half2float(ct[(size_t)rl * EPI_PITCH + d]);
            float t2 = __half2float(ct[(size_t)rl * EPI_PITCH + d + 64]);
            size_t o = ((size_t)((bq * NHEADS + head) * SEQ + sq)) * HD;
            if (region < 2) {
                float cs = g_cos[sq * 64 + d];
                float sn = g_sin[sq * 64 + d];
                dst[o + d]      = __float2half_rn(t1 * cs - t2 * sn);
                dst[o + d + 64] = __float2half_rn(t2 * cs + t1 * sn);
            } else {
                dst[o + d]      = __float2half_rn(t1);
                dst[o + d + 64] = __float2half_rn(t2);
            }
        }
    }
}

// ---------------- relative-position bias table (pre-scaled by log2 e) ----------------
__global__ void bias_kernel(const float* __restrict__ rel)
{
    int idx = blockIdx.x * blockDim.x + threadIdx.x;
    if (idx >= NHEADS * SEQ) return;
    int h = idx >> 11;
    int n = idx & (SEQ - 1);
    int bucket;
    if (n < 16) {
        bucket = n;
    } else {
        float val = logf((float)n * (1.f / 16.f)) / logf(8.f) * 16.f;
        int bi = (int)val + 16;
        bucket = bi < 31 ? bi : 31;
    }
    g_bias[idx] = rel[bucket * NHEADS + h] * 1.4426950408889634f;
}

// ---------------- flash attention: fp16 mma + ldmatrix, V via ldmatrix.trans --------
#define FQ   128
#define FKC  64
#define QPH  136
#define OFF_KH  (FQ * QPH)                 // 17408 halves
#define OFF_VH  (OFF_KH + 2 * FKC * QPH)   // 34816 halves
#define OFF_BB  ((OFF_VH + 2 * FKC * QPH) * 2)   // byte offset of bias floats
#define FLASH_SMEM (OFF_BB + 2 * 192 * 4)

__global__ __launch_bounds__(256, 1) void flash_mma_kernel()
{
    extern __shared__ __half smh[];
    float* biasb = (float*)((char*)smh + OFF_BB);

    const int qt = (int)gridDim.x - 1 - (int)blockIdx.x;   // heavy blocks first
    const int h = blockIdx.y, b = blockIdx.z;
    const int tid  = threadIdx.x;
    const int warp = tid >> 5, lane = tid & 31;
    const int r = lane >> 2, q = lane & 3;
    const int wr0 = warp * 16;
    const int rA = wr0 + r, rB = rA + 8;
    const uint32_t sbase = smem_u32(smh);

    const int qOff = (wr0 + (lane & 15)) * QPH + ((lane >> 4) & 1) * 8;
    const int kOff = ((lane & 7) + ((lane >> 4) & 1) * 8) * QPH + ((lane >> 3) & 1) * 8;
    const int vOff = (lane & 15) * QPH + ((lane >> 4) & 1) * 8;

    const size_t headBase = (size_t)(b * NHEADS + h) * SEQ * HD;
    const __half* Qg = g_Qh + headBase + (size_t)qt * FQ * HD;
    const float* biasH = g_bias + h * SEQ;

    const float SCL2 = 0.08838834764831845f * 1.4426950408889634f;

#pragma unroll
    for (int i = 0; i < 8; i++) {
        int f = tid + i * 256; int rr = f >> 4, c16 = f & 15;
        cp16(sbase + (uint32_t)(rr * QPH + c16 * 8) * 2u, Qg + rr * HD + c16 * 8);
    }
    CP_COMMIT();
    {
        const __half* Kg = g_Kh + headBase;
        const __half* Vg = g_Vh + headBase;
#pragma unroll
        for (int i = 0; i < 4; i++) {
            int f = tid + i * 256;
            int rr = f >> 4, c16 = f & 15;
            cp16(sbase + (uint32_t)(OFF_KH + rr * QPH + c16 * 8) * 2u, Kg + rr * HD + c16 * 8);
            cp16(sbase + (uint32_t)(OFF_VH + rr * QPH + c16 * 8) * 2u, Vg + rr * HD + c16 * 8);
        }
        if (tid < 192) {
            int dl = qt * FQ + tid - 63;
            cp4(sbase + (uint32_t)OFF_BB + tid * 4u, biasH + (dl >= 0 ? dl : 0));
        }
        CP_COMMIT();
    }
    CP_WAIT1();                        // Q resident
    __syncthreads();

    uint32_t qf[8][4];
#pragma unroll
    for (int g = 0; g < 8; g++)
        ldm_x4(qf[g], sbase + (uint32_t)(qOff + g * 16) * 2u);

    float m0 = -1e30f, m1 = -1e30f, l0 = 0.f, l1 = 0.f;
    float of[16][4];
#pragma unroll
    for (int nt = 0; nt < 16; nt++)
#pragma unroll
        for (int e = 0; e < 4; e++) of[nt][e] = 0.f;

    const int NT = 2 * qt + 2;

    for (int kt = 0; kt < NT; ++kt) {
        __syncthreads();
        if (kt + 1 < NT) {
            const int ns = (kt + 1) & 1;
            const __half* Kg = g_Kh + headBase + (size_t)(kt + 1) * FKC * HD;
            const __half* Vg = g_Vh + headBase + (size_t)(kt + 1) * FKC * HD;
#pragma unroll
            for (int i = 0; i < 4; i++) {
                int f = tid + i * 256;
                int rr = f >> 4, c16 = f & 15;
                cp16(sbase + (uint32_t)(OFF_KH + ns * FKC * QPH + rr * QPH + c16 * 8) * 2u,
                     Kg + rr * HD + c16 * 8);
                cp16(sbase + (uint32_t)(OFF_VH + ns * FKC * QPH + rr * QPH + c16 * 8) * 2u,
                     Vg + rr * HD + c16 * 8);
            }
            if (tid < 192) {
                int dl = qt * FQ - (kt + 1) * FKC + tid - 63;
                cp4(sbase + (uint32_t)OFF_BB + (ns * 192 + tid) * 4u,
                    biasH + (dl >= 0 ? dl : 0));
            }
            CP_COMMIT();
            CP_WAIT1();
        } else {
            CP_WAIT0();
        }
        __syncthreads();

        const int base = qt * FQ - kt * FKC;
        if (base < -(wr0 + 15)) continue;       // fully-masked warp

        uint32_t kBase = sbase + (uint32_t)(OFF_KH + (kt & 1) * FKC * QPH) * 2u;
        uint32_t vBase = sbase + (uint32_t)(OFF_VH + (kt & 1) * FKC * QPH) * 2u;
        const float* bsm = biasb + (kt & 1) * 192;

        float s[8][4];
#pragma unroll
        for (int nt = 0; nt < 8; nt++)
#pragma unroll
            for (int e = 0; e < 4; e++) s[nt][e] = 0.f;

#pragma unroll
        for (int g = 0; g < 8; g++) {
#pragma unroll
            for (int p = 0; p < 4; p++) {
                uint32_t bt[4];
                ldm_x4(bt, kBase + (uint32_t)(kOff + p * 16 * QPH + g * 16) * 2u);
                mma16816(s[2 * p],     qf[g], &bt[0]);
                mma16816(s[2 * p + 1], qf[g], &bt[2]);
            }
        }

        const bool dg = (base < FQ);
#pragma unroll
        for (int nt = 0; nt < 8; nt++) {
            int lc = nt * 8 + 2 * q;
            float v0 = s[nt][0] * SCL2 + bsm[rA - lc + 63];
            float v1 = s[nt][1] * SCL2 + bsm[rA - lc + 62];
            float v2 = s[nt][2] * SCL2 + bsm[rB - lc + 63];
            float v3 = s[nt][3] * SCL2 + bsm[rB - lc + 62];
            s[nt][0] = (dg && lc     > rA + base) ? -1e30f : v0;
            s[nt][1] = (dg && lc + 1 > rA + base) ? -1e30f : v1;
            s[nt][2] = (dg && lc     > rB + base) ? -1e30f : v2;
            s[nt][3] = (dg && lc + 1 > rB + base) ? -1e30f : v3;
        }

        float mxA = -1e30f, mxB = -1e30f;
#pragma unroll
        for (int nt = 0; nt < 8; nt++) {
            mxA = fmaxf(mxA, fmaxf(s[nt][0], s[nt][1]));
            mxB = fmaxf(mxB, fmaxf(s[nt][2], s[nt][3]));
        }
        mxA = fmaxf(mxA, __shfl_xor_sync(0xFFFFFFFFu, mxA, 1));
        mxA = fmaxf(mxA, __shfl_xor_sync(0xFFFFFFFFu, mxA, 2));
        mxB = fmaxf(mxB, __shfl_xor_sync(0xFFFFFFFFu, mxB, 1));
        mxB = fmaxf(mxB, __shfl_xor_sync(0xFFFFFFFFu, mxB, 2));
        float mn0 = fmaxf(m0, mxA), mn1 = fmaxf(m1, mxB);
        float c0 = exp2f(m0 - mn0), c1 = exp2f(m1 - mn1);
        m0 = mn0; m1 = mn1;

        float sA = 0.f, sB = 0.f;
#pragma unroll
        for (int nt = 0; nt < 8; nt++) {
            s[nt][0] = exp2f(s[nt][0] - mn0);
            s[nt][1] = exp2f(s[nt][1] - mn0);
            s[nt][2] = exp2f(s[nt][2] - mn1);
            s[nt][3] = exp2f(s[nt][3] - mn1);
            sA += s[nt][0] + s[nt][1];
            sB += s[nt][2] + s[nt][3];
        }

#pragma unroll
        for (int nt = 0; nt < 16; nt++) {
            of[nt][0] *= c0; of[nt][1] *= c0;
            of[nt][2] *= c1; of[nt][3] *= c1;
        }

#pragma unroll
        for (int g = 0; g < 4; g++) {
            uint32_t pa[4];
            pa[0] = packh2(s[2 * g][0],     s[2 * g][1]);
            pa[1] = packh2(s[2 * g][2],     s[2 * g][3]);
            pa[2] = packh2(s[2 * g + 1][0], s[2 * g + 1][1]);
            pa[3] = packh2(s[2 * g + 1][2], s[2 * g + 1][3]);
#pragma unroll
            for (int p = 0; p < 8; p++) {
                uint32_t bt[4];
                ldm_x4_t(bt, vBase + (uint32_t)(vOff + g * 16 * QPH + p * 16) * 2u);
                mma16816(of[2 * p],     pa, &bt[0]);
                mma16816(of[2 * p + 1], pa, &bt[2]);
            }
        }

        sA += __shfl_xor_sync(0xFFFFFFFFu, sA, 1);
        sA += __shfl_xor_sync(0xFFFFFFFFu, sA, 2);
        sB += __shfl_xor_sync(0xFFFFFFFFu, sB, 1);
        sB += __shfl_xor_sync(0xFFFFFFFFu, sB, 2);
        l0 = l0 * c0 + sA;
        l1 = l1 * c1 + sB;
    }

    float li0 = 1.f / l0, li1 = 1.f / l1;
    int growA = qt * FQ + rA, growB = qt * FQ + rB;
#pragma unroll
    for (int nt = 0; nt < 16; nt++) {
        int col = h * HD + nt * 8 + 2 * q;
        *(__half2*)&g_ctxh[(size_t)(b * SEQ + growA) * HID + col] =
            __floats2half2_rn(of[nt][0] * li0, of[nt][1] * li0);
        *(__half2*)&g_ctxh[(size_t)(b * SEQ + growB) * HID + col] =
            __floats2half2_rn(of[nt][2] * li1, of[nt][3] * li1);
    }
}

// ---------------- launch ----------------
extern "C" void kernel_launch(void* const* d_in, const int* in_sizes, int n_in,
                              void* d_out, int out_size)
{
    const float* x    = (const float*)d_in[0];   // [B,S,H]
    const float* qkvw = (const float*)d_in[1];   // [H, 3H]
    const float* dw   = (const float*)d_in[2];   // [H, H]
    const float* rel  = (const float*)d_in[3];   // [32, 16]
    float* out = (float*)d_out;

    __half *p_ctxh, *p_xh, *p_wqkvh, *p_dwh;
    cudaGetSymbolAddress((void**)&p_ctxh,  g_ctxh);
    cudaGetSymbolAddress((void**)&p_xh,    g_xh);
    cudaGetSymbolAddress((void**)&p_wqkvh, g_wqkvh);
    cudaGetSymbolAddress((void**)&p_dwh,   g_dwh);

    cudaFuncSetAttribute((const void*)gemm_h<__half, true>,
                         cudaFuncAttributeMaxDynamicSharedMemorySize, GEMM_SMEM);
    cudaFuncSetAttribute((const void*)gemm_h<float, false>,
                         cudaFuncAttributeMaxDynamicSharedMemorySize, GEMM_SMEM);
    cudaFuncSetAttribute(flash_mma_kernel, cudaFuncAttributeMaxDynamicSharedMemorySize, FLASH_SMEM);

    // Launch order keeps QKV GEMM as the 4th launch (ncu capture slot).
    rope_table_kernel<<<(SEQ * 64) / 256, 256>>>();
    transpose_h_kernel<<<dim3(3 * HID / 32, HID / 32), 256>>>(qkvw, p_wqkvh, HID, 3 * HID);
    convert_h_kernel<<<(BATCH * SEQ * HID / 4) / 256, 256>>>(x, p_xh);
    // 4) QKV GEMM with fused RoPE + head-split epilogue  <-- profiled launch
    gemm_h<__half, true><<<dim3(3 * HID / GBN, BATCH * SEQ / GBM), 256, GEMM_SMEM>>>(
        p_xh, p_wqkvh, (__half*)nullptr, BATCH * SEQ, 3 * HID, HID);
    transpose_h_kernel<<<dim3(HID / 32, HID / 32), 256>>>(dw, p_dwh, HID, HID);
    bias_kernel<<<(NHEADS * SEQ + 255) / 256, 256>>>(rel);
    flash_mma_kernel<<<dim3(SEQ / FQ, NHEADS, BATCH), 256, FLASH_SMEM>>>();
    // dense GEMM (fp16 in, fp32 out)
    gemm_h<float, false><<<dim3(HID / GBN, BATCH * SEQ / GBM), 256, GEMM_SMEM>>>(
        p_ctxh, p_dwh, out, BATCH * SEQ, HID, HID);
}

// round 16
// speedup vs baseline: 1.0140x; 1.0140x over previous
#include <cuda_runtime.h>
#include <cuda_fp16.h>
#include <math.h>
#include <float.h>
#include <stdint.h>

#define BATCH   2
#define SEQ     2048
#define HID     2048
#define NHEADS  16
#define HD      128

// ---------------- static scratch (no allocations allowed) ----------------
__device__ __half g_qkvh [BATCH * SEQ * 3 * HID];       // [B,S,3H] fp16 (QKV gemm out)
__device__ __half g_Qh   [BATCH * NHEADS * SEQ * HD];   // [B,NH,S,D]
__device__ __half g_Kh   [BATCH * NHEADS * SEQ * HD];
__device__ __half g_Vh   [BATCH * NHEADS * SEQ * HD];   // [B,NH,S,D] (natural)
__device__ __half g_ctxh [BATCH * SEQ * HID];           // [B,S,H]
__device__ __half g_xh   [BATCH * SEQ * HID];           // fp16 x
__device__ __half g_wqkvh[3 * HID * HID];               // [3H,H]  qkv_w^T fp16
__device__ __half g_dwh  [HID * HID];                   // [H,H]   dense_w^T fp16
__device__ float  g_bias [NHEADS * SEQ];                // bias[h][q-k] * log2(e)
__device__ float  g_cos  [SEQ * 64];
__device__ float  g_sin  [SEQ * 64];

// ======================= helpers =======================
__device__ __forceinline__ uint32_t smem_u32(const void* p) {
    uint32_t a;
    asm("{ .reg .u64 t; cvta.to.shared.u64 t, %1; cvt.u32.u64 %0, t; }"
        : "=r"(a) : "l"(p));
    return a;
}
__device__ __forceinline__ void cp16(uint32_t s, const void* g) {
    asm volatile("cp.async.cg.shared.global [%0], [%1], 16;" :: "r"(s), "l"(g));
}
__device__ __forceinline__ void cp4(uint32_t s, const void* g) {
    asm volatile("cp.async.ca.shared.global [%0], [%1], 4;" :: "r"(s), "l"(g));
}
#define CP_COMMIT() asm volatile("cp.async.commit_group;" ::: "memory")
#define CP_WAIT2()  asm volatile("cp.async.wait_group 2;"  ::: "memory")
#define CP_WAIT1()  asm volatile("cp.async.wait_group 1;"  ::: "memory")
#define CP_WAIT0()  asm volatile("cp.async.wait_group 0;"  ::: "memory")

__device__ __forceinline__ uint32_t packh2(float x, float y) {
    __half2 h = __floats2half2_rn(x, y);
    return *(uint32_t*)&h;
}

// ldmatrix x4: loads 4 8x8 f16 matrices; lane groups 0-7/8-15/16-23/24-31 give row addrs.
__device__ __forceinline__ void ldm_x4(uint32_t* r, uint32_t addr) {
    asm volatile("ldmatrix.sync.aligned.m8n8.x4.shared.b16 {%0,%1,%2,%3}, [%4];"
        : "=r"(r[0]), "=r"(r[1]), "=r"(r[2]), "=r"(r[3]) : "r"(addr));
}
// trans variant: each 8x8 tile transposed in-flight.
__device__ __forceinline__ void ldm_x4_t(uint32_t* r, uint32_t addr) {
    asm volatile("ldmatrix.sync.aligned.m8n8.x4.trans.shared.b16 {%0,%1,%2,%3}, [%4];"
        : "=r"(r[0]), "=r"(r[1]), "=r"(r[2]), "=r"(r[3]) : "r"(addr));
}

// fp16 mma: D(f32) += A(f16 m16k16, row) * B(f16 k16n8, col)
__device__ __forceinline__ void mma16816(float* d, const uint32_t* a, const uint32_t* b) {
    asm volatile(
        "mma.sync.aligned.m16n8k16.row.col.f32.f16.f16.f32 "
        "{%0,%1,%2,%3}, {%4,%5,%6,%7}, {%8,%9}, {%0,%1,%2,%3};"
        : "+f"(d[0]), "+f"(d[1]), "+f"(d[2]), "+f"(d[3])
        : "r"(a[0]), "r"(a[1]), "r"(a[2]), "r"(a[3]), "r"(b[0]), "r"(b[1]));
}

// ======================= f32 -> f16 convert (elementwise) =======================
__global__ __launch_bounds__(256) void convert_h_kernel(
    const float* __restrict__ in, __half* __restrict__ out)
{
    int i = blockIdx.x * blockDim.x + threadIdx.x;
    float4 v = ((const float4*)in)[i];
    __half2* o = (__half2*)out;
    o[2 * i]     = __floats2half2_rn(v.x, v.y);
    o[2 * i + 1] = __floats2half2_rn(v.z, v.w);
}

// ======================= f32 [R][C] -> f16 [C][R] transpose =======================
__global__ __launch_bounds__(256) void transpose_h_kernel(
    const float* __restrict__ in, __half* __restrict__ out, int R, int C)
{
    __shared__ float t[32][33];
    int bx = blockIdx.x * 32, by = blockIdx.y * 32;
    int tx = threadIdx.x & 31, ty = threadIdx.x >> 5;
#pragma unroll
    for (int i = 0; i < 32; i += 8)
        t[ty + i][tx] = in[(size_t)(by + ty + i) * C + bx + tx];
    __syncthreads();
#pragma unroll
    for (int i = 0; i < 32; i += 8)
        out[(size_t)(bx + ty + i) * R + by + tx] = __float2half_rn(t[tx][ty + i]);
}

// ======================= RoPE cos/sin table =======================
__global__ __launch_bounds__(256) void rope_table_kernel()
{
    int idx = blockIdx.x * blockDim.x + threadIdx.x;   // SEQ*64
    int s = idx >> 6, d = idx & 63;
    float inv = powf(10000.f, -(float)d * (1.f / 64.f));
    float sn, cs;
    sincosf((float)s * inv, &sn, &cs);
    g_cos[idx] = cs;
    g_sin[idx] = sn;
}

// ======================= fp16 mma GEMM (R11/R13 config): 128x128, BK=32h, 4 stages, occ2
#define GBM 128
#define GBN 128
#define GBKH 32                      // k halves per chunk
#define GPITCH 40                    // halves; 80B rows -> conflict-free ldmatrix
#define STG_HALFS (2 * 128 * GPITCH) // A + B = 10240 halves = 20480 B
#define GEMM_SMEM (4 * STG_HALFS * 2)   // 81920 B -> 2 CTAs/SM

template <typename OutT>
__global__ __launch_bounds__(256, 2) void gemm_h(
    const __half* __restrict__ A, const __half* __restrict__ Bt,
    OutT* __restrict__ C, int M, int N, int K)
{
    extern __shared__ __half smh[];
    const int tid  = threadIdx.x;
    const int warp = tid >> 5, lane = tid & 31;
    const int wm = (warp >> 2) * 64;
    const int wn = (warp & 3) * 32;
    const int r  = lane >> 2;
    const int q  = lane & 3;
    const int row0 = blockIdx.y * GBM;
    const int col0 = blockIdx.x * GBN;
    const uint32_t sb = smem_u32(smh);
    const int NC = K / GBKH;

    const int aOff = (wm + (lane & 15)) * GPITCH + ((lane >> 4) & 1) * 8;
    const int bOff = (wn + (lane & 7) + ((lane >> 4) & 1) * 8) * GPITCH
                   + ((lane >> 3) & 1) * 8;

    float cf[4][4][4];
#pragma unroll
    for (int i = 0; i < 4; i++)
#pragma unroll
        for (int j = 0; j < 4; j++)
#pragma unroll
            for (int t = 0; t < 4; t++) cf[i][j][t] = 0.f;

    const int lrow = tid >> 1;
    const int lseg = (tid & 1) * 2;

    auto load_stage = [&](int c, int s) {
        uint32_t base = sb + (uint32_t)(s * STG_HALFS) * 2u;
#pragma unroll
        for (int j = 0; j < 2; j++) {
            int seg = lseg + j;
            cp16(base + (uint32_t)(lrow * GPITCH + seg * 8) * 2u,
                 A + (size_t)(row0 + lrow) * K + c * GBKH + seg * 8);
            cp16(base + (uint32_t)(128 * GPITCH + lrow * GPITCH + seg * 8) * 2u,
                 Bt + (size_t)(col0 + lrow) * K + c * GBKH + seg * 8);
        }
        CP_COMMIT();
    };

    load_stage(0, 0);
    load_stage(1, 1);
    load_stage(2, 2);

    for (int c = 0; c < NC; ++c) {
        CP_WAIT2();
        __syncthreads();
        int nc = c + 3;
        if (nc < NC) load_stage(nc, nc & 3); else CP_COMMIT();

        uint32_t aBase = sb + (uint32_t)((c & 3) * STG_HALFS) * 2u;
        uint32_t bBase = aBase + (uint32_t)(128 * GPITCH) * 2u;
#pragma unroll
        for (int step = 0; step < 2; step++) {
            const int kk = step * 16;
            uint32_t af[4][4], bt[2][4];
#pragma unroll
            for (int mt = 0; mt < 4; mt++)
                ldm_x4(af[mt], aBase + (uint32_t)(aOff + mt * 16 * GPITCH + kk) * 2u);
#pragma unroll
            for (int p = 0; p < 2; p++)
                ldm_x4(bt[p], bBase + (uint32_t)(bOff + p * 16 * GPITCH + kk) * 2u);
#pragma unroll
            for (int mt = 0; mt < 4; mt++) {
                mma16816(cf[mt][0], af[mt], &bt[0][0]);
                mma16816(cf[mt][1], af[mt], &bt[0][2]);
                mma16816(cf[mt][2], af[mt], &bt[1][0]);
                mma16816(cf[mt][3], af[mt], &bt[1][2]);
            }
        }
    }

#pragma unroll
    for (int mt = 0; mt < 4; mt++) {
        int row = row0 + wm + mt * 16 + r;
#pragma unroll
        for (int nt = 0; nt < 4; nt++) {
            int col = col0 + wn + nt * 8 + 2 * q;
            if (sizeof(OutT) == 2) {
                *(__half2*)((__half*)C + (size_t)row * N + col) =
                    __floats2half2_rn(cf[mt][nt][0], cf[mt][nt][1]);
                *(__half2*)((__half*)C + (size_t)(row + 8) * N + col) =
                    __floats2half2_rn(cf[mt][nt][2], cf[mt][nt][3]);
            } else {
                *(float2*)((float*)C + (size_t)row * N + col) =
                    make_float2(cf[mt][nt][0], cf[mt][nt][1]);
                *(float2*)((float*)C + (size_t)(row + 8) * N + col) =
                    make_float2(cf[mt][nt][2], cf[mt][nt][3]);
            }
        }
    }
}

// ---------------- RoPE + split (fp16 in/out) ----------------
__global__ __launch_bounds__(256) void rope_split_kernel()
{
    int t = blockIdx.x * blockDim.x + threadIdx.x;
    int d = t & 63;
    int h = (t >> 6) & (NHEADS - 1);
    int s = (t >> 10) & (SEQ - 1);
    int b = t >> 21;

    const __half* base = g_qkvh + ((size_t)(b * SEQ + s)) * (3 * HID) + h * HD;
    float q1 = __half2float(base[d]),            q2 = __half2float(base[d + 64]);
    float k1 = __half2float(base[HID + d]),      k2 = __half2float(base[HID + d + 64]);
    float v1 = __half2float(base[2 * HID + d]),  v2 = __half2float(base[2 * HID + d + 64]);

    float cs = g_cos[s * 64 + d];
    float sn = g_sin[s * 64 + d];

    size_t o = ((size_t)((b * NHEADS + h) * SEQ + s)) * HD;
    g_Qh[o + d]      = __float2half_rn(q1 * cs - q2 * sn);
    g_Qh[o + d + 64] = __float2half_rn(q2 * cs + q1 * sn);
    g_Kh[o + d]      = __float2half_rn(k1 * cs - k2 * sn);
    g_Kh[o + d + 64] = __float2half_rn(k2 * cs + k1 * sn);
    g_Vh[o + d]      = __float2half_rn(v1);
    g_Vh[o + d + 64] = __float2half_rn(v2);
}

// ---------------- relative-position bias table (pre-scaled by log2 e) ----------------
__global__ void bias_kernel(const float* __restrict__ rel)
{
    int idx = blockIdx.x * blockDim.x + threadIdx.x;
    if (idx >= NHEADS * SEQ) return;
    int h = idx >> 11;
    int n = idx & (SEQ - 1);
    int bucket;
    if (n < 16) {
        bucket = n;
    } else {
        float val = logf((float)n * (1.f / 16.f)) / logf(8.f) * 16.f;
        int bi = (int)val + 16;
        bucket = bi < 31 ? bi : 31;
    }
    g_bias[idx] = rel[bucket * NHEADS + h] * 1.4426950408889634f;
}

// ---------------- flash attention: fp16 mma + ldmatrix, 3-stage K/V, 1 sync/tile ----
// 128 q-rows per block, 64 k-cols per iter. Q/K/V all [row][d] pitch 136.
#define FQ   128
#define FKC  64
#define QPH  136
#define KSTG (FKC * QPH)                   // 8704 halves per K (or V) stage
#define OFF_KH  (FQ * QPH)                 // 17408 halves
#define OFF_VH  (OFF_KH + 3 * KSTG)        // 43520 halves
#define OFF_BB  ((OFF_VH + 3 * KSTG) * 2)  // byte offset of bias floats: 139264
#define FLASH_SMEM (OFF_BB + 3 * 192 * 4)  // 141568 B

__global__ __launch_bounds__(256, 1) void flash_mma_kernel()
{
    extern __shared__ __half smh[];
    float* biasb = (float*)((char*)smh + OFF_BB);

    const int qt = (int)gridDim.x - 1 - (int)blockIdx.x;   // heavy blocks first
    const int h = blockIdx.y, b = blockIdx.z;
    const int tid  = threadIdx.x;
    const int warp = tid >> 5, lane = tid & 31;
    const int r = lane >> 2, q = lane & 3;
    const int wr0 = warp * 16;
    const int rA = wr0 + r, rB = rA + 8;
    const uint32_t sbase = smem_u32(smh);

    const int qOff = (wr0 + (lane & 15)) * QPH + ((lane >> 4) & 1) * 8;
    const int kOff = ((lane & 7) + ((lane >> 4) & 1) * 8) * QPH + ((lane >> 3) & 1) * 8;
    const int vOff = (lane & 15) * QPH + ((lane >> 4) & 1) * 8;

    const size_t headBase = (size_t)(b * NHEADS + h) * SEQ * HD;
    const __half* Qg = g_Qh + headBase + (size_t)qt * FQ * HD;
    const __half* Kg0 = g_Kh + headBase;
    const __half* Vg0 = g_Vh + headBase;
    const float* biasH = g_bias + h * SEQ;

    const float SCL2 = 0.08838834764831845f * 1.4426950408889634f;
    const int NT = 2 * qt + 2;

    // KV tile loader (stage = kt % 3), bundled with its bias diagonal
    auto load_kv = [&](int kt) {
        const int st = kt % 3;
        const __half* Kg = Kg0 + (size_t)kt * FKC * HD;
        const __half* Vg = Vg0 + (size_t)kt * FKC * HD;
#pragma unroll
        for (int i = 0; i < 4; i++) {
            int f = tid + i * 256;
            int rr = f >> 4, c16 = f & 15;
            cp16(sbase + (uint32_t)(OFF_KH + st * KSTG + rr * QPH + c16 * 8) * 2u,
                 Kg + rr * HD + c16 * 8);
            cp16(sbase + (uint32_t)(OFF_VH + st * KSTG + rr * QPH + c16 * 8) * 2u,
                 Vg + rr * HD + c16 * 8);
        }
        if (tid < 192) {
            int dl = qt * FQ - kt * FKC + tid - 63;
            cp4(sbase + (uint32_t)OFF_BB + (st * 192 + tid) * 4u,
                biasH + (dl >= 0 ? dl : 0));
        }
        CP_COMMIT();
    };

    // prolog: Q (group 0), KV0 (group 1), KV1 (group 2; NT>=2 always)
#pragma unroll
    for (int i = 0; i < 8; i++) {
        int f = tid + i * 256; int rr = f >> 4, c16 = f & 15;
        cp16(sbase + (uint32_t)(rr * QPH + c16 * 8) * 2u, Qg + rr * HD + c16 * 8);
    }
    CP_COMMIT();
    load_kv(0);
    load_kv(1);

    CP_WAIT2();                        // Q resident (KV0, KV1 may pend)
    __syncthreads();

    uint32_t qf[8][4];
#pragma unroll
    for (int g = 0; g < 8; g++)
        ldm_x4(qf[g], sbase + (uint32_t)(qOff + g * 16) * 2u);

    float m0 = -1e30f, m1 = -1e30f, l0 = 0.f, l1 = 0.f;
    float of[16][4];
#pragma unroll
    for (int nt = 0; nt < 16; nt++)
#pragma unroll
        for (int e = 0; e < 4; e++) of[nt][e] = 0.f;

    for (int kt = 0; kt < NT; ++kt) {
        // wait for KV(kt); KV(kt+1) may stay in flight
        if (kt + 1 < NT) CP_WAIT1(); else CP_WAIT0();
        __syncthreads();               // data visible to all; prior stage reads done
        if (kt + 2 < NT) load_kv(kt + 2);   // writes stage (kt+2)%3, last read at kt-1

        const int base = qt * FQ - kt * FKC;
        if (base < -(wr0 + 15)) continue;   // fully-masked warp

        const int st = kt % 3;
        uint32_t kBase = sbase + (uint32_t)(OFF_KH + st * KSTG) * 2u;
        uint32_t vBase = sbase + (uint32_t)(OFF_VH + st * KSTG) * 2u;
        const float* bsm = biasb + st * 192;

        // ---- S = Q K^T (16 x 64 per warp)
        float s[8][4];
#pragma unroll
        for (int nt = 0; nt < 8; nt++)
#pragma unroll
            for (int e = 0; e < 4; e++) s[nt][e] = 0.f;

#pragma unroll
        for (int g = 0; g < 8; g++) {
#pragma unroll
            for (int p = 0; p < 4; p++) {
                uint32_t bt[4];
                ldm_x4(bt, kBase + (uint32_t)(kOff + p * 16 * QPH + g * 16) * 2u);
                mma16816(s[2 * p],     qf[g], &bt[0]);
                mma16816(s[2 * p + 1], qf[g], &bt[2]);
            }
        }

        // ---- scale + bias + causal mask
        const bool dg = (base < FQ);
#pragma unroll
        for (int nt = 0; nt < 8; nt++) {
            int lc = nt * 8 + 2 * q;
            float v0 = s[nt][0] * SCL2 + bsm[rA - lc + 63];
            float v1 = s[nt][1] * SCL2 + bsm[rA - lc + 62];
            float v2 = s[nt][2] * SCL2 + bsm[rB - lc + 63];
            float v3 = s[nt][3] * SCL2 + bsm[rB - lc + 62];
            s[nt][0] = (dg && lc     > rA + base) ? -1e30f : v0;
            s[nt][1] = (dg && lc + 1 > rA + base) ? -1e30f : v1;
            s[nt][2] = (dg && lc     > rB + base) ? -1e30f : v2;
            s[nt][3] = (dg && lc + 1 > rB + base) ? -1e30f : v3;
        }

        // ---- row max within quad
        float mxA = -1e30f, mxB = -1e30f;
#pragma unroll
        for (int nt = 0; nt < 8; nt++) {
            mxA = fmaxf(mxA, fmaxf(s[nt][0], s[nt][1]));
            mxB = fmaxf(mxB, fmaxf(s[nt][2], s[nt][3]));
        }
        mxA = fmaxf(mxA, __shfl_xor_sync(0xFFFFFFFFu, mxA, 1));
        mxA = fmaxf(mxA, __shfl_xor_sync(0xFFFFFFFFu, mxA, 2));
        mxB = fmaxf(mxB, __shfl_xor_sync(0xFFFFFFFFu, mxB, 1));
        mxB = fmaxf(mxB, __shfl_xor_sync(0xFFFFFFFFu, mxB, 2));
        float mn0 = fmaxf(m0, mxA), mn1 = fmaxf(m1, mxB);
        float c0 = exp2f(m0 - mn0), c1 = exp2f(m1 - mn1);
        m0 = mn0; m1 = mn1;

        // ---- P = exp2(s - m); partial sums
        float sA = 0.f, sB = 0.f;
#pragma unroll
        for (int nt = 0; nt < 8; nt++) {
            s[nt][0] = exp2f(s[nt][0] - mn0);
            s[nt][1] = exp2f(s[nt][1] - mn0);
            s[nt][2] = exp2f(s[nt][2] - mn1);
            s[nt][3] = exp2f(s[nt][3] - mn1);
            sA += s[nt][0] + s[nt][1];
            sB += s[nt][2] + s[nt][3];
        }

        // ---- rescale O
#pragma unroll
        for (int nt = 0; nt < 16; nt++) {
            of[nt][0] *= c0; of[nt][1] *= c0;
            of[nt][2] *= c1; of[nt][3] *= c1;
        }

        // ---- O += P V : P in A-frag layout; V b-frags via ldmatrix.trans
#pragma unroll
        for (int g = 0; g < 4; g++) {
            uint32_t pa[4];
            pa[0] = packh2(s[2 * g][0],     s[2 * g][1]);
            pa[1] = packh2(s[2 * g][2],     s[2 * g][3]);
            pa[2] = packh2(s[2 * g + 1][0], s[2 * g + 1][1]);
            pa[3] = packh2(s[2 * g + 1][2], s[2 * g + 1][3]);
#pragma unroll
            for (int p = 0; p < 8; p++) {
                uint32_t bt[4];
                ldm_x4_t(bt, vBase + (uint32_t)(vOff + g * 16 * QPH + p * 16) * 2u);
                mma16816(of[2 * p],     pa, &bt[0]);
                mma16816(of[2 * p + 1], pa, &bt[2]);
            }
        }

        // ---- deferred row-sum reduction
        sA += __shfl_xor_sync(0xFFFFFFFFu, sA, 1);
        sA += __shfl_xor_sync(0xFFFFFFFFu, sA, 2);
        sB += __shfl_xor_sync(0xFFFFFFFFu, sB, 1);
        sB += __shfl_xor_sync(0xFFFFFFFFu, sB, 2);
        l0 = l0 * c0 + sA;
        l1 = l1 * c1 + sB;
    }

    // ---- epilogue: normalize + fp16 ctx
    float li0 = 1.f / l0, li1 = 1.f / l1;
    int growA = qt * FQ + rA, growB = qt * FQ + rB;
#pragma unroll
    for (int nt = 0; nt < 16; nt++) {
        int col = h * HD + nt * 8 + 2 * q;
        *(__half2*)&g_ctxh[(size_t)(b * SEQ + growA) * HID + col] =
            __floats2half2_rn(of[nt][0] * li0, of[nt][1] * li0);
        *(__half2*)&g_ctxh[(size_t)(b * SEQ + growB) * HID + col] =
            __floats2half2_rn(of[nt][2] * li1, of[nt][3] * li1);
    }
}

// ---------------- launch ----------------
extern "C" void kernel_launch(void* const* d_in, const int* in_sizes, int n_in,
                              void* d_out, int out_size)
{
    const float* x    = (const float*)d_in[0];   // [B,S,H]
    const float* qkvw = (const float*)d_in[1];   // [H, 3H]
    const float* dw   = (const float*)d_in[2];   // [H, H]
    const float* rel  = (const float*)d_in[3];   // [32, 16]
    float* out = (float*)d_out;

    __half *p_qkvh, *p_ctxh, *p_xh, *p_wqkvh, *p_dwh;
    cudaGetSymbolAddress((void**)&p_qkvh,  g_qkvh);
    cudaGetSymbolAddress((void**)&p_ctxh,  g_ctxh);
    cudaGetSymbolAddress((void**)&p_xh,    g_xh);
    cudaGetSymbolAddress((void**)&p_wqkvh, g_wqkvh);
    cudaGetSymbolAddress((void**)&p_dwh,   g_dwh);

    cudaFuncSetAttribute(gemm_h<__half>, cudaFuncAttributeMaxDynamicSharedMemorySize, GEMM_SMEM);
    cudaFuncSetAttribute(gemm_h<float>,  cudaFuncAttributeMaxDynamicSharedMemorySize, GEMM_SMEM);
    cudaFuncSetAttribute(flash_mma_kernel, cudaFuncAttributeMaxDynamicSharedMemorySize, FLASH_SMEM);

    // Launch order keeps QKV GEMM as the 4th launch (ncu capture slot).
    rope_table_kernel<<<(SEQ * 64) / 256, 256>>>();
    transpose_h_kernel<<<dim3(3 * HID / 32, HID / 32), 256>>>(qkvw, p_wqkvh, HID, 3 * HID);
    convert_h_kernel<<<(BATCH * SEQ * HID / 4) / 256, 256>>>(x, p_xh);
    // 4) QKV GEMM (fp16 mma + ldmatrix)  <-- profiled launch
    gemm_h<__half><<<dim3(3 * HID / GBN, BATCH * SEQ / GBM), 256, GEMM_SMEM>>>(
        p_xh, p_wqkvh, p_qkvh, BATCH * SEQ, 3 * HID, HID);
    transpose_h_kernel<<<dim3(HID / 32, HID / 32), 256>>>(dw, p_dwh, HID, HID);
    rope_split_kernel<<<(BATCH * SEQ * NHEADS * 64) / 256, 256>>>();
    bias_kernel<<<(NHEADS * SEQ + 255) / 256, 256>>>(rel);
    flash_mma_kernel<<<dim3(SEQ / FQ, NHEADS, BATCH), 256, FLASH_SMEM>>>();
    // dense GEMM (fp16 in, fp32 out)
    gemm_h<float><<<dim3(HID / GBN, BATCH * SEQ / GBM), 256, GEMM_SMEM>>>(
        p_ctxh, p_dwh, out, BATCH * SEQ, HID, HID);
}

// round 17
// speedup vs baseline: 1.0337x; 1.0194x over previous
#include <cuda_runtime.h>
#include <cuda_fp16.h>
#include <math.h>
#include <float.h>
#include <stdint.h>

#define BATCH   2
#define SEQ     2048
#define HID     2048
#define NHEADS  16
#define HD      128

// ---------------- static scratch (no allocations allowed) ----------------
__device__ __half g_qkvh [BATCH * SEQ * 3 * HID];       // [B,S,3H] fp16 (QKV gemm out)
__device__ __half g_Qh   [BATCH * NHEADS * SEQ * HD];   // [B,NH,S,D]
__device__ __half g_Kh   [BATCH * NHEADS * SEQ * HD];
__device__ __half g_Vh   [BATCH * NHEADS * SEQ * HD];   // [B,NH,S,D] (natural)
__device__ __half g_ctxh [BATCH * SEQ * HID];           // [B,S,H]
__device__ __half g_xh   [BATCH * SEQ * HID];           // fp16 x
__device__ __half g_wqkvh[3 * HID * HID];               // [3H,H]  qkv_w^T fp16
__device__ __half g_dwh  [HID * HID];                   // [H,H]   dense_w^T fp16
__device__ float  g_bias [NHEADS * SEQ];                // bias[h][q-k] * log2(e)
__device__ float  g_cos  [SEQ * 64];
__device__ float  g_sin  [SEQ * 64];

// ======================= helpers =======================
__device__ __forceinline__ uint32_t smem_u32(const void* p) {
    uint32_t a;
    asm("{ .reg .u64 t; cvta.to.shared.u64 t, %1; cvt.u32.u64 %0, t; }"
        : "=r"(a) : "l"(p));
    return a;
}
__device__ __forceinline__ void cp16(uint32_t s, const void* g) {
    asm volatile("cp.async.cg.shared.global [%0], [%1], 16;" :: "r"(s), "l"(g));
}
__device__ __forceinline__ void cp4(uint32_t s, const void* g) {
    asm volatile("cp.async.ca.shared.global [%0], [%1], 4;" :: "r"(s), "l"(g));
}
#define CP_COMMIT() asm volatile("cp.async.commit_group;" ::: "memory")
#define CP_WAIT2()  asm volatile("cp.async.wait_group 2;"  ::: "memory")
#define CP_WAIT1()  asm volatile("cp.async.wait_group 1;"  ::: "memory")
#define CP_WAIT0()  asm volatile("cp.async.wait_group 0;"  ::: "memory")

__device__ __forceinline__ uint32_t packh2(float x, float y) {
    __half2 h = __floats2half2_rn(x, y);
    return *(uint32_t*)&h;
}

// ldmatrix x4: loads 4 8x8 f16 matrices; lane groups 0-7/8-15/16-23/24-31 give row addrs.
__device__ __forceinline__ void ldm_x4(uint32_t* r, uint32_t addr) {
    asm volatile("ldmatrix.sync.aligned.m8n8.x4.shared.b16 {%0,%1,%2,%3}, [%4];"
        : "=r"(r[0]), "=r"(r[1]), "=r"(r[2]), "=r"(r[3]) : "r"(addr));
}
// trans variant: each 8x8 tile transposed in-flight.
__device__ __forceinline__ void ldm_x4_t(uint32_t* r, uint32_t addr) {
    asm volatile("ldmatrix.sync.aligned.m8n8.x4.trans.shared.b16 {%0,%1,%2,%3}, [%4];"
        : "=r"(r[0]), "=r"(r[1]), "=r"(r[2]), "=r"(r[3]) : "r"(addr));
}

// fp16 mma: D(f32) += A(f16 m16k16, row) * B(f16 k16n8, col)
__device__ __forceinline__ void mma16816(float* d, const uint32_t* a, const uint32_t* b) {
    asm volatile(
        "mma.sync.aligned.m16n8k16.row.col.f32.f16.f16.f32 "
        "{%0,%1,%2,%3}, {%4,%5,%6,%7}, {%8,%9}, {%0,%1,%2,%3};"
        : "+f"(d[0]), "+f"(d[1]), "+f"(d[2]), "+f"(d[3])
        : "r"(a[0]), "r"(a[1]), "r"(a[2]), "r"(a[3]), "r"(b[0]), "r"(b[1]));
}

// ======================= f32 -> f16 convert (elementwise) =======================
__global__ __launch_bounds__(256) void convert_h_kernel(
    const float* __restrict__ in, __half* __restrict__ out)
{
    int i = blockIdx.x * blockDim.x + threadIdx.x;
    float4 v = ((const float4*)in)[i];
    __half2* o = (__half2*)out;
    o[2 * i]     = __floats2half2_rn(v.x, v.y);
    o[2 * i + 1] = __floats2half2_rn(v.z, v.w);
}

// ======================= f32 [R][C] -> f16 [C][R] transpose =======================
__global__ __launch_bounds__(256) void transpose_h_kernel(
    const float* __restrict__ in, __half* __restrict__ out, int R, int C)
{
    __shared__ float t[32][33];
    int bx = blockIdx.x * 32, by = blockIdx.y * 32;
    int tx = threadIdx.x & 31, ty = threadIdx.x >> 5;
#pragma unroll
    for (int i = 0; i < 32; i += 8)
        t[ty + i][tx] = in[(size_t)(by + ty + i) * C + bx + tx];
    __syncthreads();
#pragma unroll
    for (int i = 0; i < 32; i += 8)
        out[(size_t)(bx + ty + i) * R + by + tx] = __float2half_rn(t[tx][ty + i]);
}

// ======================= RoPE cos/sin table =======================
__global__ __launch_bounds__(256) void rope_table_kernel()
{
    int idx = blockIdx.x * blockDim.x + threadIdx.x;   // SEQ*64
    int s = idx >> 6, d = idx & 63;
    float inv = powf(10000.f, -(float)d * (1.f / 64.f));
    float sn, cs;
    sincosf((float)s * inv, &sn, &cs);
    g_cos[idx] = cs;
    g_sin[idx] = sn;
}

// ======================= fp16 mma GEMM (R11/R13 config): 128x128, BK=32h, 4 stages, occ2
#define GBM 128
#define GBN 128
#define GBKH 32                      // k halves per chunk
#define GPITCH 40                    // halves; 80B rows -> conflict-free ldmatrix
#define STG_HALFS (2 * 128 * GPITCH) // A + B = 10240 halves = 20480 B
#define GEMM_SMEM (4 * STG_HALFS * 2)   // 81920 B -> 2 CTAs/SM

template <typename OutT>
__global__ __launch_bounds__(256, 2) void gemm_h(
    const __half* __restrict__ A, const __half* __restrict__ Bt,
    OutT* __restrict__ C, int M, int N, int K)
{
    extern __shared__ __half smh[];
    const int tid  = threadIdx.x;
    const int warp = tid >> 5, lane = tid & 31;
    const int wm = (warp >> 2) * 64;
    const int wn = (warp & 3) * 32;
    const int r  = lane >> 2;
    const int q  = lane & 3;
    const int row0 = blockIdx.y * GBM;
    const int col0 = blockIdx.x * GBN;
    const uint32_t sb = smem_u32(smh);
    const int NC = K / GBKH;

    const int aOff = (wm + (lane & 15)) * GPITCH + ((lane >> 4) & 1) * 8;
    const int bOff = (wn + (lane & 7) + ((lane >> 4) & 1) * 8) * GPITCH
                   + ((lane >> 3) & 1) * 8;

    float cf[4][4][4];
#pragma unroll
    for (int i = 0; i < 4; i++)
#pragma unroll
        for (int j = 0; j < 4; j++)
#pragma unroll
            for (int t = 0; t < 4; t++) cf[i][j][t] = 0.f;

    const int lrow = tid >> 1;
    const int lseg = (tid & 1) * 2;

    auto load_stage = [&](int c, int s) {
        uint32_t base = sb + (uint32_t)(s * STG_HALFS) * 2u;
#pragma unroll
        for (int j = 0; j < 2; j++) {
            int seg = lseg + j;
            cp16(base + (uint32_t)(lrow * GPITCH + seg * 8) * 2u,
                 A + (size_t)(row0 + lrow) * K + c * GBKH + seg * 8);
            cp16(base + (uint32_t)(128 * GPITCH + lrow * GPITCH + seg * 8) * 2u,
                 Bt + (size_t)(col0 + lrow) * K + c * GBKH + seg * 8);
        }
        CP_COMMIT();
    };

    load_stage(0, 0);
    load_stage(1, 1);
    load_stage(2, 2);

    for (int c = 0; c < NC; ++c) {
        CP_WAIT2();
        __syncthreads();
        int nc = c + 3;
        if (nc < NC) load_stage(nc, nc & 3); else CP_COMMIT();

        uint32_t aBase = sb + (uint32_t)((c & 3) * STG_HALFS) * 2u;
        uint32_t bBase = aBase + (uint32_t)(128 * GPITCH) * 2u;
#pragma unroll
        for (int step = 0; step < 2; step++) {
            const int kk = step * 16;
            uint32_t af[4][4], bt[2][4];
#pragma unroll
            for (int mt = 0; mt < 4; mt++)
                ldm_x4(af[mt], aBase + (uint32_t)(aOff + mt * 16 * GPITCH + kk) * 2u);
#pragma unroll
            for (int p = 0; p < 2; p++)
                ldm_x4(bt[p], bBase + (uint32_t)(bOff + p * 16 * GPITCH + kk) * 2u);
#pragma unroll
            for (int mt = 0; mt < 4; mt++) {
                mma16816(cf[mt][0], af[mt], &bt[0][0]);
                mma16816(cf[mt][1], af[mt], &bt[0][2]);
                mma16816(cf[mt][2], af[mt], &bt[1][0]);
                mma16816(cf[mt][3], af[mt], &bt[1][2]);
            }
        }
    }

#pragma unroll
    for (int mt = 0; mt < 4; mt++) {
        int row = row0 + wm + mt * 16 + r;
#pragma unroll
        for (int nt = 0; nt < 4; nt++) {
            int col = col0 + wn + nt * 8 + 2 * q;
            if (sizeof(OutT) == 2) {
                *(__half2*)((__half*)C + (size_t)row * N + col) =
                    __floats2half2_rn(cf[mt][nt][0], cf[mt][nt][1]);
                *(__half2*)((__half*)C + (size_t)(row + 8) * N + col) =
                    __floats2half2_rn(cf[mt][nt][2], cf[mt][nt][3]);
            } else {
                *(float2*)((float*)C + (size_t)row * N + col) =
                    make_float2(cf[mt][nt][0], cf[mt][nt][1]);
                *(float2*)((float*)C + (size_t)(row + 8) * N + col) =
                    make_float2(cf[mt][nt][2], cf[mt][nt][3]);
            }
        }
    }
}

// ---------------- RoPE + split (fp16 in/out, half2 vectorized) ----------------
__global__ __launch_bounds__(256) void rope_split_kernel()
{
    int t = blockIdx.x * blockDim.x + threadIdx.x;   // B*S*NH*32 threads
    int d = (t & 31) * 2;                            // even d
    int h = (t >> 5) & (NHEADS - 1);
    int s = (t >> 9) & (SEQ - 1);
    int b = t >> 20;

    const __half* base = g_qkvh + ((size_t)(b * SEQ + s)) * (3 * HID) + h * HD;
    __half2 q1 = *(const __half2*)(base + d);
    __half2 q2 = *(const __half2*)(base + d + 64);
    __half2 k1 = *(const __half2*)(base + HID + d);
    __half2 k2 = *(const __half2*)(base + HID + d + 64);
    __half2 vv1 = *(const __half2*)(base + 2 * HID + d);
    __half2 vv2 = *(const __half2*)(base + 2 * HID + d + 64);

    float2 cs = *(const float2*)(g_cos + s * 64 + d);
    float2 sn = *(const float2*)(g_sin + s * 64 + d);

    float q1x = __half2float(q1.x), q1y = __half2float(q1.y);
    float q2x = __half2float(q2.x), q2y = __half2float(q2.y);
    float k1x = __half2float(k1.x), k1y = __half2float(k1.y);
    float k2x = __half2float(k2.x), k2y = __half2float(k2.y);

    size_t o = ((size_t)((b * NHEADS + h) * SEQ + s)) * HD;
    *(__half2*)(g_Qh + o + d) =
        __floats2half2_rn(q1x * cs.x - q2x * sn.x, q1y * cs.y - q2y * sn.y);
    *(__half2*)(g_Qh + o + d + 64) =
        __floats2half2_rn(q2x * cs.x + q1x * sn.x, q2y * cs.y + q1y * sn.y);
    *(__half2*)(g_Kh + o + d) =
        __floats2half2_rn(k1x * cs.x - k2x * sn.x, k1y * cs.y - k2y * sn.y);
    *(__half2*)(g_Kh + o + d + 64) =
        __floats2half2_rn(k2x * cs.x + k1x * sn.x, k2y * cs.y + k1y * sn.y);
    *(__half2*)(g_Vh + o + d)      = vv1;
    *(__half2*)(g_Vh + o + d + 64) = vv2;
}

// ---------------- relative-position bias table (pre-scaled by log2 e) ----------------
__global__ void bias_kernel(const float* __restrict__ rel)
{
    int idx = blockIdx.x * blockDim.x + threadIdx.x;
    if (idx >= NHEADS * SEQ) return;
    int h = idx >> 11;
    int n = idx & (SEQ - 1);
    int bucket;
    if (n < 16) {
        bucket = n;
    } else {
        float val = logf((float)n * (1.f / 16.f)) / logf(8.f) * 16.f;
        int bi = (int)val + 16;
        bucket = bi < 31 ? bi : 31;
    }
    g_bias[idx] = rel[bucket * NHEADS + h] * 1.4426950408889634f;
}

// ---------------- flash attention: FQ=64, 128 threads, occ 2 ----------------
// 64 q-rows per block, 64 k-cols per iter. Q/K/V all [row][d] pitch 136.
#define FQ   64
#define FKC  64
#define QPH  136
#define KSTG (FKC * QPH)                   // 8704 halves per stage per operand
#define OFF_KH  (FQ * QPH)                 // 8704 halves (Q tile end)
#define OFF_VH  (OFF_KH + 2 * KSTG)        // 26112
#define OFF_BB  ((OFF_VH + 2 * KSTG) * 2)  // byte offset of bias floats: 87040
#define FLASH_SMEM (OFF_BB + 2 * 128 * 4)  // 88064 B -> 2 CTAs/SM

__global__ __launch_bounds__(128, 2) void flash_mma_kernel()
{
    extern __shared__ __half smh[];
    float* biasb = (float*)((char*)smh + OFF_BB);

    const int qt = (int)gridDim.x - 1 - (int)blockIdx.x;   // heavy blocks first
    const int h = blockIdx.y, b = blockIdx.z;
    const int tid  = threadIdx.x;          // 0..127
    const int warp = tid >> 5, lane = tid & 31;
    const int r = lane >> 2, q = lane & 3;
    const int wr0 = warp * 16;             // warp owns rows wr0..wr0+15 (of 64)
    const int rA = wr0 + r, rB = rA + 8;
    const uint32_t sbase = smem_u32(smh);

    const int qOff = (wr0 + (lane & 15)) * QPH + ((lane >> 4) & 1) * 8;
    const int kOff = ((lane & 7) + ((lane >> 4) & 1) * 8) * QPH + ((lane >> 3) & 1) * 8;
    const int vOff = (lane & 15) * QPH + ((lane >> 4) & 1) * 8;

    const size_t headBase = (size_t)(b * NHEADS + h) * SEQ * HD;
    const __half* Qg  = g_Qh + headBase + (size_t)qt * FQ * HD;
    const __half* Kg0 = g_Kh + headBase;
    const __half* Vg0 = g_Vh + headBase;
    const float* biasH = g_bias + h * SEQ;

    const float SCL2 = 0.08838834764831845f * 1.4426950408889634f;
    const int NT = qt + 1;

    // KV tile loader (stage = kt & 1), bundled with its 128-entry bias diagonal
    auto load_kv = [&](int kt) {
        const int st = kt & 1;
        const __half* Kg = Kg0 + (size_t)kt * FKC * HD;
        const __half* Vg = Vg0 + (size_t)kt * FKC * HD;
#pragma unroll
        for (int i = 0; i < 8; i++) {
            int f = tid + i * 128;
            int rr = f >> 4, c16 = f & 15;
            cp16(sbase + (uint32_t)(OFF_KH + st * KSTG + rr * QPH + c16 * 8) * 2u,
                 Kg + rr * HD + c16 * 8);
            cp16(sbase + (uint32_t)(OFF_VH + st * KSTG + rr * QPH + c16 * 8) * 2u,
                 Vg + rr * HD + c16 * 8);
        }
        {
            int dl = (qt - kt) * FKC + tid - 63;
            cp4(sbase + (uint32_t)OFF_BB + (st * 128 + tid) * 4u,
                biasH + (dl >= 0 ? dl : 0));
        }
        CP_COMMIT();
    };

    // prolog: Q (group 0), KV0 (group 1)
#pragma unroll
    for (int i = 0; i < 8; i++) {
        int f = tid + i * 128; int rr = f >> 4, c16 = f & 15;
        cp16(sbase + (uint32_t)(rr * QPH + c16 * 8) * 2u, Qg + rr * HD + c16 * 8);
    }
    CP_COMMIT();
    load_kv(0);

    CP_WAIT1();                        // Q resident (KV0 may pend)
    __syncthreads();

    uint32_t qf[8][4];
#pragma unroll
    for (int g = 0; g < 8; g++)
        ldm_x4(qf[g], sbase + (uint32_t)(qOff + g * 16) * 2u);

    float m0 = -1e30f, m1 = -1e30f, l0 = 0.f, l1 = 0.f;
    float of[16][4];
#pragma unroll
    for (int nt = 0; nt < 16; nt++)
#pragma unroll
        for (int e = 0; e < 4; e++) of[nt][e] = 0.f;

    for (int kt = 0; kt < NT; ++kt) {
        __syncthreads();               // all warps done reading stage (kt+1)&1
        if (kt + 1 < NT) {
            load_kv(kt + 1);
            CP_WAIT1();                // KV[kt] complete (KV[kt+1] in flight)
        } else {
            CP_WAIT0();
        }
        __syncthreads();               // data visible to all threads

        const int st = kt & 1;
        uint32_t kBase = sbase + (uint32_t)(OFF_KH + st * KSTG) * 2u;
        uint32_t vBase = sbase + (uint32_t)(OFF_VH + st * KSTG) * 2u;
        const float* bsm = biasb + st * 128;

        // ---- S = Q K^T (16 x 64 per warp)
        float s[8][4];
#pragma unroll
        for (int nt = 0; nt < 8; nt++)
#pragma unroll
            for (int e = 0; e < 4; e++) s[nt][e] = 0.f;

#pragma unroll
        for (int g = 0; g < 8; g++) {
#pragma unroll
            for (int p = 0; p < 4; p++) {
                uint32_t bt[4];
                ldm_x4(bt, kBase + (uint32_t)(kOff + p * 16 * QPH + g * 16) * 2u);
                mma16816(s[2 * p],     qf[g], &bt[0]);
                mma16816(s[2 * p + 1], qf[g], &bt[2]);
            }
        }

        // ---- scale + bias + causal mask (diagonal tile only)
        const bool dg = (kt == qt);
#pragma unroll
        for (int nt = 0; nt < 8; nt++) {
            int lc = nt * 8 + 2 * q;
            float v0 = s[nt][0] * SCL2 + bsm[rA - lc + 63];
            float v1 = s[nt][1] * SCL2 + bsm[rA - lc + 62];
            float v2 = s[nt][2] * SCL2 + bsm[rB - lc + 63];
            float v3 = s[nt][3] * SCL2 + bsm[rB - lc + 62];
            s[nt][0] = (dg && lc     > rA) ? -1e30f : v0;
            s[nt][1] = (dg && lc + 1 > rA) ? -1e30f : v1;
            s[nt][2] = (dg && lc     > rB) ? -1e30f : v2;
            s[nt][3] = (dg && lc + 1 > rB) ? -1e30f : v3;
        }

        // ---- row max within quad
        float mxA = -1e30f, mxB = -1e30f;
#pragma unroll
        for (int nt = 0; nt < 8; nt++) {
            mxA = fmaxf(mxA, fmaxf(s[nt][0], s[nt][1]));
            mxB = fmaxf(mxB, fmaxf(s[nt][2], s[nt][3]));
        }
        mxA = fmaxf(mxA, __shfl_xor_sync(0xFFFFFFFFu, mxA, 1));
        mxA = fmaxf(mxA, __shfl_xor_sync(0xFFFFFFFFu, mxA, 2));
        mxB = fmaxf(mxB, __shfl_xor_sync(0xFFFFFFFFu, mxB, 1));
        mxB = fmaxf(mxB, __shfl_xor_sync(0xFFFFFFFFu, mxB, 2));
        float mn0 = fmaxf(m0, mxA), mn1 = fmaxf(m1, mxB);
        float c0 = exp2f(m0 - mn0), c1 = exp2f(m1 - mn1);
        m0 = mn0; m1 = mn1;

        // ---- P = exp2(s - m); partial sums
        float sA = 0.f, sB = 0.f;
#pragma unroll
        for (int nt = 0; nt < 8; nt++) {
            s[nt][0] = exp2f(s[nt][0] - mn0);
            s[nt][1] = exp2f(s[nt][1] - mn0);
            s[nt][2] = exp2f(s[nt][2] - mn1);
            s[nt][3] = exp2f(s[nt][3] - mn1);
            sA += s[nt][0] + s[nt][1];
            sB += s[nt][2] + s[nt][3];
        }

        // ---- rescale O
#pragma unroll
        for (int nt = 0; nt < 16; nt++) {
            of[nt][0] *= c0; of[nt][1] *= c0;
            of[nt][2] *= c1; of[nt][3] *= c1;
        }

        // ---- O += P V : P in A-frag layout; V b-frags via ldmatrix.trans
#pragma unroll
        for (int g = 0; g < 4; g++) {
            uint32_t pa[4];
            pa[0] = packh2(s[2 * g][0],     s[2 * g][1]);
            pa[1] = packh2(s[2 * g][2],     s[2 * g][3]);
            pa[2] = packh2(s[2 * g + 1][0], s[2 * g + 1][1]);
            pa[3] = packh2(s[2 * g + 1][2], s[2 * g + 1][3]);
#pragma unroll
            for (int p = 0; p < 8; p++) {
                uint32_t bt[4];
                ldm_x4_t(bt, vBase + (uint32_t)(vOff + g * 16 * QPH + p * 16) * 2u);
                mma16816(of[2 * p],     pa, &bt[0]);
                mma16816(of[2 * p + 1], pa, &bt[2]);
            }
        }

        // ---- deferred row-sum reduction
        sA += __shfl_xor_sync(0xFFFFFFFFu, sA, 1);
        sA += __shfl_xor_sync(0xFFFFFFFFu, sA, 2);
        sB += __shfl_xor_sync(0xFFFFFFFFu, sB, 1);
        sB += __shfl_xor_sync(0xFFFFFFFFu, sB, 2);
        l0 = l0 * c0 + sA;
        l1 = l1 * c1 + sB;
    }

    // ---- epilogue: normalize + fp16 ctx
    float li0 = 1.f / l0, li1 = 1.f / l1;
    int growA = qt * FQ + rA, growB = qt * FQ + rB;
#pragma unroll
    for (int nt = 0; nt < 16; nt++) {
        int col = h * HD + nt * 8 + 2 * q;
        *(__half2*)&g_ctxh[(size_t)(b * SEQ + growA) * HID + col] =
            __floats2half2_rn(of[nt][0] * li0, of[nt][1] * li0);
        *(__half2*)&g_ctxh[(size_t)(b * SEQ + growB) * HID + col] =
            __floats2half2_rn(of[nt][2] * li1, of[nt][3] * li1);
    }
}

// ---------------- launch ----------------
extern "C" void kernel_launch(void* const* d_in, const int* in_sizes, int n_in,
                              void* d_out, int out_size)
{
    const float* x    = (const float*)d_in[0];   // [B,S,H]
    const float* qkvw = (const float*)d_in[1];   // [H, 3H]
    const float* dw   = (const float*)d_in[2];   // [H, H]
    const float* rel  = (const float*)d_in[3];   // [32, 16]
    float* out = (float*)d_out;

    __half *p_qkvh, *p_ctxh, *p_xh, *p_wqkvh, *p_dwh;
    cudaGetSymbolAddress((void**)&p_qkvh,  g_qkvh);
    cudaGetSymbolAddress((void**)&p_ctxh,  g_ctxh);
    cudaGetSymbolAddress((void**)&p_xh,    g_xh);
    cudaGetSymbolAddress((void**)&p_wqkvh, g_wqkvh);
    cudaGetSymbolAddress((void**)&p_dwh,   g_dwh);

    cudaFuncSetAttribute(gemm_h<__half>, cudaFuncAttributeMaxDynamicSharedMemorySize, GEMM_SMEM);
    cudaFuncSetAttribute(gemm_h<float>,  cudaFuncAttributeMaxDynamicSharedMemorySize, GEMM_SMEM);
    cudaFuncSetAttribute(flash_mma_kernel, cudaFuncAttributeMaxDynamicSharedMemorySize, FLASH_SMEM);

    // Launch order keeps QKV GEMM as the 4th launch (ncu capture slot).
    rope_table_kernel<<<(SEQ * 64) / 256, 256>>>();
    transpose_h_kernel<<<dim3(3 * HID / 32, HID / 32), 256>>>(qkvw, p_wqkvh, HID, 3 * HID);
    convert_h_kernel<<<(BATCH * SEQ * HID / 4) / 256, 256>>>(x, p_xh);
    // 4) QKV GEMM (fp16 mma + ldmatrix)  <-- profiled launch
    gemm_h<__half><<<dim3(3 * HID / GBN, BATCH * SEQ / GBM), 256, GEMM_SMEM>>>(
        p_xh, p_wqkvh, p_qkvh, BATCH * SEQ, 3 * HID, HID);
    transpose_h_kernel<<<dim3(HID / 32, HID / 32), 256>>>(dw, p_dwh, HID, HID);
    rope_split_kernel<<<(BATCH * SEQ * NHEADS * 32) / 256, 256>>>();
    bias_kernel<<<(NHEADS * SEQ + 255) / 256, 256>>>(rel);
    flash_mma_kernel<<<dim3(SEQ / FQ, NHEADS, BATCH), 128, FLASH_SMEM>>>();
    // dense GEMM (fp16 in, fp32 out)
    gemm_h<float><<<dim3(HID / GBN, BATCH * SEQ / GBM), 256, GEMM_SMEM>>>(
        p_ctxh, p_dwh, out, BATCH * SEQ, HID, HID);
}